// round 1
// baseline (speedup 1.0000x reference)
#include <cuda_runtime.h>

#define NN 50000
#define EE 800000

// ---------------- scratch (static device globals; no allocs) ----------------
__device__ float g_m1[NN * 128];
__device__ float g_q1[NN * 128];
__device__ float g_p1[NN * 128];
__device__ float g_m2[NN * 128];
__device__ float g_q2[NN * 64];
__device__ float g_p2[NN * 64];
__device__ int   g_rowptr[NN + 1];
__device__ int   g_cursor[NN];
__device__ int   g_esrc[EE];

__device__ __forceinline__ float gelu_f(float x) {
    return 0.5f * x * (1.0f + erff(x * 0.70710678118654752440f));
}

// ---------------- CSR build ----------------
__global__ void zero_k() {
    int i = blockIdx.x * blockDim.x + threadIdx.x;
    if (i < NN) g_cursor[i] = 0;
}

__global__ void hist_k(const int* __restrict__ dst) {
    int e = blockIdx.x * blockDim.x + threadIdx.x;
    if (e < EE) atomicAdd(&g_cursor[dst[e]], 1);
}

// single-block exclusive scan of g_cursor -> g_rowptr; re-zeros g_cursor
__global__ __launch_bounds__(1024) void scan_k() {
    __shared__ int warpsum[32];
    __shared__ int s_carry;
    __shared__ int s_tot;
    int tid = threadIdx.x, lane = tid & 31, wid = tid >> 5;
    if (tid == 0) s_carry = 0;
    __syncthreads();
    for (int base = 0; base < NN; base += 8192) {
        int idx0 = base + tid * 8;
        int v[8]; int tot = 0;
#pragma unroll
        for (int j = 0; j < 8; j++) {
            int id = idx0 + j;
            v[j] = (id < NN) ? g_cursor[id] : 0;
            tot += v[j];
        }
        int incl = tot;
#pragma unroll
        for (int off = 1; off < 32; off <<= 1) {
            int t = __shfl_up_sync(0xffffffffu, incl, off);
            if (lane >= off) incl += t;
        }
        if (lane == 31) warpsum[wid] = incl;
        __syncthreads();
        if (wid == 0) {
            int w = warpsum[lane];
            int wi = w;
#pragma unroll
            for (int off = 1; off < 32; off <<= 1) {
                int t = __shfl_up_sync(0xffffffffu, wi, off);
                if (lane >= off) wi += t;
            }
            warpsum[lane] = wi - w;   // exclusive
            if (lane == 31) s_tot = wi;
        }
        __syncthreads();
        int run = s_carry + warpsum[wid] + (incl - tot);
#pragma unroll
        for (int j = 0; j < 8; j++) {
            int id = idx0 + j;
            if (id < NN) { g_rowptr[id] = run; g_cursor[id] = 0; }
            run += v[j];
        }
        __syncthreads();
        if (tid == 0) s_carry += s_tot;
        __syncthreads();
    }
    if (threadIdx.x == 0) g_rowptr[NN] = s_carry;
}

__global__ void scatter_k(const int* __restrict__ src, const int* __restrict__ dst) {
    int e = blockIdx.x * blockDim.x + threadIdx.x;
    if (e < EE) {
        int d = dst[e];
        int pos = g_rowptr[d] + atomicAdd(&g_cursor[d], 1);
        g_esrc[pos] = src[e];
    }
}

// ---------------- fp32 GEMM: C[M,ncols] = act(A[M,128] @ W[128,ncols] + bias) ----
// BM=128, BN=64, BK=16, 256 threads, 8x4 per thread
__global__ __launch_bounds__(256) void gemm128_k(
    const float* __restrict__ A, const float* __restrict__ W,
    const float* __restrict__ bias, float* __restrict__ C,
    int M, int ncols, int act)
{
    __shared__ float As[16][132];
    __shared__ float Bs[16][64];
    const int tid = threadIdx.x;
    const int tx = tid & 15, ty = tid >> 4;
    const int rowBase = blockIdx.x * 128;
    const int colBase = blockIdx.y * 64;

    float acc[8][4];
#pragma unroll
    for (int i = 0; i < 8; i++)
#pragma unroll
        for (int j = 0; j < 4; j++) acc[i][j] = 0.f;

    const int ar = tid >> 2;          // 0..63
    const int ak = (tid & 3) * 4;     // 0,4,8,12
    const int bk = tid >> 4;          // 0..15
    const int bc = (tid & 15) * 4;    // 0..60

    for (int k0 = 0; k0 < 128; k0 += 16) {
#pragma unroll
        for (int h = 0; h < 2; h++) {
            int r = rowBase + ar + h * 64;
            if (r >= M) r = M - 1;     // clamp; store is guarded
            float4 v = *(const float4*)(A + (size_t)r * 128 + (k0 + ak));
            As[ak + 0][ar + h * 64] = v.x;
            As[ak + 1][ar + h * 64] = v.y;
            As[ak + 2][ar + h * 64] = v.z;
            As[ak + 3][ar + h * 64] = v.w;
        }
        float4 wv = *(const float4*)(W + (size_t)(k0 + bk) * ncols + colBase + bc);
        *(float4*)&Bs[bk][bc] = wv;
        __syncthreads();
#pragma unroll
        for (int k = 0; k < 16; k++) {
            float4 a0 = *(const float4*)&As[k][ty * 8];
            float4 a1 = *(const float4*)&As[k][ty * 8 + 4];
            float4 bb = *(const float4*)&Bs[k][tx * 4];
            float av_[8] = {a0.x, a0.y, a0.z, a0.w, a1.x, a1.y, a1.z, a1.w};
            float bv_[4] = {bb.x, bb.y, bb.z, bb.w};
#pragma unroll
            for (int i = 0; i < 8; i++)
#pragma unroll
                for (int j = 0; j < 4; j++)
                    acc[i][j] = fmaf(av_[i], bv_[j], acc[i][j]);
        }
        __syncthreads();
    }

    float4 bb = *(const float4*)(bias + colBase + tx * 4);
#pragma unroll
    for (int i = 0; i < 8; i++) {
        int r = rowBase + ty * 8 + i;
        if (r < M) {
            float4 o;
            o.x = acc[i][0] + bb.x;
            o.y = acc[i][1] + bb.y;
            o.z = acc[i][2] + bb.z;
            o.w = acc[i][3] + bb.w;
            if (act) {
                o.x = gelu_f(o.x); o.y = gelu_f(o.y);
                o.z = gelu_f(o.z); o.w = gelu_f(o.w);
            }
            *(float4*)(C + (size_t)r * ncols + colBase + tx * 4) = o;
        }
    }
}

// ---------------- edge kernels: one warp per dst node, fused softmax-agg ----
// out[dst] = gelu( (sum_e es*p[src]) / (sum_e es) + bg )     (d = 128)
__global__ __launch_bounds__(256) void edge128_k(
    const float* __restrict__ q, const float* __restrict__ p,
    const float* __restrict__ a, const float* __restrict__ bg,
    float* __restrict__ out)
{
    int gw = (blockIdx.x * 256 + threadIdx.x) >> 5;
    if (gw >= NN) return;
    int lane = threadIdx.x & 31;
    int c = lane * 4;
    float4 qv = *(const float4*)(q + (size_t)gw * 128 + c);
    float4 av = *(const float4*)(a + c);
    float ax = 0.f, ay = 0.f, az = 0.f, aw = 0.f;
    float denom = 0.f;
    int i = g_rowptr[gw];
    int end = g_rowptr[gw + 1];
    if (i < end) {
        int s = g_esrc[i];
        float4 pv = *(const float4*)(p + (size_t)s * 128 + c);
        while (1) {
            float4 pvn;
            if (i + 1 < end) {
                int sn = g_esrc[i + 1];
                pvn = *(const float4*)(p + (size_t)sn * 128 + c);
            }
            float tx = qv.x + pv.x; tx = tx > 0.f ? tx : 0.2f * tx;
            float ty = qv.y + pv.y; ty = ty > 0.f ? ty : 0.2f * ty;
            float tz = qv.z + pv.z; tz = tz > 0.f ? tz : 0.2f * tz;
            float tw = qv.w + pv.w; tw = tw > 0.f ? tw : 0.2f * tw;
            float part = fmaf(tx, av.x, fmaf(ty, av.y, fmaf(tz, av.z, tw * av.w)));
#pragma unroll
            for (int off = 16; off > 0; off >>= 1)
                part += __shfl_xor_sync(0xffffffffu, part, off);
            float es = __expf(part);
            denom += es;
            ax = fmaf(es, pv.x, ax);
            ay = fmaf(es, pv.y, ay);
            az = fmaf(es, pv.z, az);
            aw = fmaf(es, pv.w, aw);
            i++;
            if (i >= end) break;
            pv = pvn;
        }
    }
    float inv = denom > 0.f ? 1.0f / denom : 0.f;
    float4 bv = *(const float4*)(bg + c);
    float4 o;
    o.x = gelu_f(fmaf(ax, inv, bv.x));
    o.y = gelu_f(fmaf(ay, inv, bv.y));
    o.z = gelu_f(fmaf(az, inv, bv.z));
    o.w = gelu_f(fmaf(aw, inv, bv.w));
    *(float4*)(out + (size_t)gw * 128 + c) = o;
}

// out[dst] = (sum_e es*p[src]) / (sum_e es) + b_out          (d = 64)
__global__ __launch_bounds__(256) void edge64_k(
    const float* __restrict__ q, const float* __restrict__ p,
    const float* __restrict__ a, const float* __restrict__ bo,
    float* __restrict__ out)
{
    int gw = (blockIdx.x * 256 + threadIdx.x) >> 5;
    if (gw >= NN) return;
    int lane = threadIdx.x & 31;
    int c = lane * 2;
    float2 qv = *(const float2*)(q + (size_t)gw * 64 + c);
    float2 av = *(const float2*)(a + c);
    float ax = 0.f, ay = 0.f;
    float denom = 0.f;
    int i = g_rowptr[gw];
    int end = g_rowptr[gw + 1];
    if (i < end) {
        int s = g_esrc[i];
        float2 pv = *(const float2*)(p + (size_t)s * 64 + c);
        while (1) {
            float2 pvn;
            if (i + 1 < end) {
                int sn = g_esrc[i + 1];
                pvn = *(const float2*)(p + (size_t)sn * 64 + c);
            }
            float tx = qv.x + pv.x; tx = tx > 0.f ? tx : 0.2f * tx;
            float ty = qv.y + pv.y; ty = ty > 0.f ? ty : 0.2f * ty;
            float part = fmaf(tx, av.x, ty * av.y);
#pragma unroll
            for (int off = 16; off > 0; off >>= 1)
                part += __shfl_xor_sync(0xffffffffu, part, off);
            float es = __expf(part);
            denom += es;
            ax = fmaf(es, pv.x, ax);
            ay = fmaf(es, pv.y, ay);
            i++;
            if (i >= end) break;
            pv = pvn;
        }
    }
    float inv = denom > 0.f ? 1.0f / denom : 0.f;
    float2 bv = *(const float2*)(bo + c);
    float2 o;
    o.x = fmaf(ax, inv, bv.x);
    o.y = fmaf(ay, inv, bv.y);
    *(float2*)(out + (size_t)gw * 64 + c) = o;
}

// ---------------- launch ----------------
extern "C" void kernel_launch(void* const* d_in, const int* in_sizes, int n_in,
                              void* d_out, int out_size)
{
    const float* x    = (const float*)d_in[0];
    const float* W0   = (const float*)d_in[1];
    const float* b0   = (const float*)d_in[2];
    const float* Wq1  = (const float*)d_in[3];
    const float* bq1  = (const float*)d_in[4];
    const float* Wp1  = (const float*)d_in[5];
    const float* bp1  = (const float*)d_in[6];
    const float* a1   = (const float*)d_in[7];
    const float* bg2  = (const float*)d_in[8];
    const float* Wq2  = (const float*)d_in[9];
    const float* bq2  = (const float*)d_in[10];
    const float* Wp2  = (const float*)d_in[11];
    const float* bp2  = (const float*)d_in[12];
    const float* a2   = (const float*)d_in[13];
    const float* bout = (const float*)d_in[14];
    const int*   src  = (const int*)d_in[15];
    const int*   dst  = (const int*)d_in[16];
    float* out = (float*)d_out;

    float *pm1, *pq1, *pp1, *pm2, *pq2, *pp2;
    cudaGetSymbolAddress((void**)&pm1, g_m1);
    cudaGetSymbolAddress((void**)&pq1, g_q1);
    cudaGetSymbolAddress((void**)&pp1, g_p1);
    cudaGetSymbolAddress((void**)&pm2, g_m2);
    cudaGetSymbolAddress((void**)&pq2, g_q2);
    cudaGetSymbolAddress((void**)&pp2, g_p2);

    // CSR build (dst-segmented edge lists)
    zero_k<<<(NN + 255) / 256, 256>>>();
    hist_k<<<(EE + 255) / 256, 256>>>(dst);
    scan_k<<<1, 1024>>>();
    scatter_k<<<(EE + 255) / 256, 256>>>(src, dst);

    dim3 g2((NN + 127) / 128, 2);
    dim3 g1((NN + 127) / 128, 1);

    // layer 1
    gemm128_k<<<g2, 256>>>(x,   W0,  b0,  pm1, NN, 128, 1);   // m1 = gelu(x@W0+b0)
    gemm128_k<<<g2, 256>>>(pm1, Wq1, bq1, pq1, NN, 128, 0);   // q1
    gemm128_k<<<g2, 256>>>(pm1, Wp1, bp1, pp1, NN, 128, 0);   // p1
    edge128_k<<<(NN * 32 + 255) / 256, 256>>>(pq1, pp1, a1, bg2, pm2);  // m2 = gelu(h1+bg2)

    // layer 2
    gemm128_k<<<g1, 256>>>(pm2, Wq2, bq2, pq2, NN, 64, 0);    // q2
    gemm128_k<<<g1, 256>>>(pm2, Wp2, bp2, pp2, NN, 64, 0);    // p2
    edge64_k<<<(NN * 32 + 255) / 256, 256>>>(pq2, pp2, a2, bout, out);  // out = h2+b_out
}